// round 7
// baseline (speedup 1.0000x reference)
#include <cuda_runtime.h>
#include <cuda_bf16.h>
#include <cstdint>

// Problem constants (fixed shapes)
#define CELLS 4096
#define BATCH 256
#define FIN   160
#define FHID  192
#define KC    32          // K-chunk (5 chunks of 32 = 160, no padding)
#define NCHUNK 5

// SMEM: double-buffered bf16 operand tiles, padded stride 40 bf16 (80 B)
// -> conflict-free for both STS (row-major 16B stores) and frag LDS.
#define ASTRIDE 80        // bytes per row (32 bf16 data + 8 bf16 pad)
#define AHI 0             // A hi : 256 rows x 80 B = 20480
#define ALO 20480         // A lo : 20480
#define BHI 40960         // B hi : 192 rows x 80 B = 15360
#define BLO 56320         // B lo : 15360
#define BUFSZ 71680
#define SM_PSUM (2*BUFSZ)             // float[192][8]
#define SM_PSQ  (SM_PSUM + 6144)      // float[192][8]
#define SM_PA   (SM_PSQ  + 6144)     // float[192]
#define SM_PB   (SM_PA + 768)
#define SM_PW   (SM_PB + 768)
#define SMEM_TOTAL (SM_PW + 768)      // 157952 bytes

// m16n8k16 bf16 HMMA, fp32 accumulate (sm_80+ : compiles on plain compute_103)
#define MMA(d, a, b0, b1)                                                    \
    asm volatile(                                                            \
        "mma.sync.aligned.m16n8k16.row.col.f32.bf16.bf16.f32 "               \
        "{%0,%1,%2,%3}, {%4,%5,%6,%7}, {%8,%9}, {%0,%1,%2,%3};"              \
        : "+f"((d)[0]), "+f"((d)[1]), "+f"((d)[2]), "+f"((d)[3])             \
        : "r"((a)[0]), "r"((a)[1]), "r"((a)[2]), "r"((a)[3]),                \
          "r"(b0), "r"(b1))

// 8 fp32 -> packed bf16 hi + bf16 lo (3xBF16 precision-recovery split)
static __device__ __forceinline__ void cvt8(const float4& A, const float4& B,
                                            uint4& hi, uint4& lo) {
    float f[8] = {A.x, A.y, A.z, A.w, B.x, B.y, B.z, B.w};
    unsigned h[4], l[4];
#pragma unroll
    for (int j = 0; j < 4; j++) {
        __nv_bfloat162 hp = __floats2bfloat162_rn(f[2 * j], f[2 * j + 1]);
        float r0 = f[2 * j]     - __bfloat162float(hp.x);
        float r1 = f[2 * j + 1] - __bfloat162float(hp.y);
        __nv_bfloat162 lp = __floats2bfloat162_rn(r0, r1);
        h[j] = *reinterpret_cast<unsigned*>(&hp);
        l[j] = *reinterpret_cast<unsigned*>(&lp);
    }
    hi = make_uint4(h[0], h[1], h[2], h[3]);
    lo = make_uint4(l[0], l[1], l[2], l[3]);
}

// Store one A slot (8 k-values of one row) as hi/lo bf16 into a chunk buffer
static __device__ __forceinline__ void stsA(char* buf, int slot,
                                            const float4& v0, const float4& v1) {
    int row = slot >> 2, gg = slot & 3;
    uint4 hi, lo;
    cvt8(v0, v1, hi, lo);
    unsigned off = (unsigned)(row * ASTRIDE + gg * 16);
    *reinterpret_cast<uint4*>(buf + AHI + off) = hi;
    *reinterpret_cast<uint4*>(buf + ALO + off) = lo;
}
static __device__ __forceinline__ void stsB(char* buf, int slot,
                                            const float4& v0, const float4& v1) {
    int row = slot >> 2, gg = slot & 3;
    uint4 hi, lo;
    cvt8(v0, v1, hi, lo);
    unsigned off = (unsigned)(row * ASTRIDE + gg * 16);
    *reinterpret_cast<uint4*>(buf + BHI + off) = hi;
    *reinterpret_cast<uint4*>(buf + BLO + off) = lo;
}

__global__ void __launch_bounds__(256, 1)
mmlp_kernel(const float* __restrict__ x, const float* __restrict__ W1,
            const float* __restrict__ gamma, const float* __restrict__ beta,
            const float* __restrict__ W2, const float* __restrict__ b2,
            float* __restrict__ out) {
    extern __shared__ char smem[];
    const int tid = threadIdx.x;
    const int lid = tid & 31;
    const int w   = tid >> 5;          // warp id: owns batch rows [32w, 32w+32)
    const int c   = blockIdx.x;
    const int g_  = lid >> 2;          // fragment group row
    const int c4  = (lid & 3) * 4;     // fragment k-pair byte offset

    // C accumulators: warp tile 32(M) x 192(N) -> 2 m-tiles x 24 n-tiles x 4
    float acc[2][24][4];
#pragma unroll
    for (int mt = 0; mt < 2; mt++)
#pragma unroll
        for (int nt = 0; nt < 24; nt++)
#pragma unroll
            for (int j = 0; j < 4; j++) acc[mt][nt][j] = 0.f;

    // ---- Prologue: stage chunk 0 into buffer 0 ----
    {
        char* buf = smem;
#pragma unroll
        for (int q = 0; q < 4; q++) {
            int slot = tid + q * 256;               // 1024 A slots
            int row = slot >> 2, gg = slot & 3;
            const float4* p = reinterpret_cast<const float4*>(
                x + ((size_t)row * CELLS + c) * FIN + gg * 8);
            stsA(buf, slot, p[0], p[1]);
        }
#pragma unroll
        for (int q = 0; q < 3; q++) {
            int slot = tid + q * 256;               // 768 B slots
            int o = slot >> 2, gg = slot & 3;
            const float4* p = reinterpret_cast<const float4*>(
                W1 + ((size_t)c * FHID + o) * FIN + gg * 8);
            stsB(buf, slot, p[0], p[1]);
        }
    }
    __syncthreads();

    // ---- Mainloop: 5 K-chunks, double-buffered, prefetch interleaved ----
#pragma unroll 1
    for (int i = 0; i < NCHUNK; i++) {
        char* cur = smem + (i & 1) * BUFSZ;
        char* nxt = smem + ((i + 1) & 1) * BUFSZ;
        const bool pf = (i + 1 < NCHUNK);
        const int k1 = (i + 1) * KC;

        // Prefetch A for next chunk (LDG issued early, consumed after kstep0)
        float4 pfa[4][2];
        if (pf) {
#pragma unroll
            for (int q = 0; q < 4; q++) {
                int slot = tid + q * 256;
                int row = slot >> 2, gg = slot & 3;
                const float4* p = reinterpret_cast<const float4*>(
                    x + ((size_t)row * CELLS + c) * FIN + k1 + gg * 8);
                pfa[q][0] = p[0];
                pfa[q][1] = p[1];
            }
        }
        float4 pfb[3][2];

#pragma unroll
        for (int kk = 0; kk < 2; kk++) {
            // A fragments for this k-step (hi + lo, 2 m-tiles)
            // Row address includes this warp's M offset (w * 32).
            unsigned ah[2][4], al[2][4];
#pragma unroll
            for (int mt = 0; mt < 2; mt++) {
                unsigned r0 = (unsigned)((w * 32 + mt * 16 + g_) * ASTRIDE +
                                         kk * 32 + c4);
                unsigned r1 = r0 + 8 * ASTRIDE;
                ah[mt][0] = *reinterpret_cast<const unsigned*>(cur + AHI + r0);
                ah[mt][1] = *reinterpret_cast<const unsigned*>(cur + AHI + r1);
                ah[mt][2] = *reinterpret_cast<const unsigned*>(cur + AHI + r0 + 16);
                ah[mt][3] = *reinterpret_cast<const unsigned*>(cur + AHI + r1 + 16);
                al[mt][0] = *reinterpret_cast<const unsigned*>(cur + ALO + r0);
                al[mt][1] = *reinterpret_cast<const unsigned*>(cur + ALO + r1);
                al[mt][2] = *reinterpret_cast<const unsigned*>(cur + ALO + r0 + 16);
                al[mt][3] = *reinterpret_cast<const unsigned*>(cur + ALO + r1 + 16);
            }
#pragma unroll
            for (int nt = 0; nt < 24; nt++) {
                unsigned bo = (unsigned)((nt * 8 + g_) * ASTRIDE + kk * 32 + c4);
                unsigned bh0 = *reinterpret_cast<const unsigned*>(cur + BHI + bo);
                unsigned bh1 = *reinterpret_cast<const unsigned*>(cur + BHI + bo + 16);
                unsigned bl0 = *reinterpret_cast<const unsigned*>(cur + BLO + bo);
                unsigned bl1 = *reinterpret_cast<const unsigned*>(cur + BLO + bo + 16);
#pragma unroll
                for (int mt = 0; mt < 2; mt++) {
                    MMA(acc[mt][nt], ah[mt], bh0, bh1);   // hi * hi
                    MMA(acc[mt][nt], ah[mt], bl0, bl1);   // hi * lo
                    MMA(acc[mt][nt], al[mt], bh0, bh1);   // lo * hi
                }
            }
            if (kk == 0 && pf) {
                // Drain A prefetch into next buffer, then issue B prefetch
#pragma unroll
                for (int q = 0; q < 4; q++)
                    stsA(nxt, tid + q * 256, pfa[q][0], pfa[q][1]);
#pragma unroll
                for (int q = 0; q < 3; q++) {
                    int slot = tid + q * 256;
                    int o = slot >> 2, gg = slot & 3;
                    const float4* p = reinterpret_cast<const float4*>(
                        W1 + ((size_t)c * FHID + o) * FIN + k1 + gg * 8);
                    pfb[q][0] = p[0];
                    pfb[q][1] = p[1];
                }
            }
        }
        if (pf) {
#pragma unroll
            for (int q = 0; q < 3; q++)
                stsB(nxt, tid + q * 256, pfb[q][0], pfb[q][1]);
        }
        __syncthreads();
    }

    // ---- Epilogue: BN stats + folded BN + relu + W2 dot, all in regs ----
    float* psum = reinterpret_cast<float*>(smem + SM_PSUM);
    float* psq  = reinterpret_cast<float*>(smem + SM_PSQ);
    float* pa   = reinterpret_cast<float*>(smem + SM_PA);
    float* pb   = reinterpret_cast<float*>(smem + SM_PB);
    float* pw   = reinterpret_cast<float*>(smem + SM_PW);

    // Per-column partial sums over this warp's 32 rows
#pragma unroll
    for (int nt = 0; nt < 24; nt++) {
        float s0 = acc[0][nt][0] + acc[0][nt][2] + acc[1][nt][0] + acc[1][nt][2];
        float s1 = acc[0][nt][1] + acc[0][nt][3] + acc[1][nt][1] + acc[1][nt][3];
        float q0 = acc[0][nt][0] * acc[0][nt][0] + acc[0][nt][2] * acc[0][nt][2] +
                   acc[1][nt][0] * acc[1][nt][0] + acc[1][nt][2] * acc[1][nt][2];
        float q1 = acc[0][nt][1] * acc[0][nt][1] + acc[0][nt][3] * acc[0][nt][3] +
                   acc[1][nt][1] * acc[1][nt][1] + acc[1][nt][3] * acc[1][nt][3];
#pragma unroll
        for (int m = 4; m <= 16; m <<= 1) {
            s0 += __shfl_xor_sync(0xFFFFFFFFu, s0, m);
            s1 += __shfl_xor_sync(0xFFFFFFFFu, s1, m);
            q0 += __shfl_xor_sync(0xFFFFFFFFu, q0, m);
            q1 += __shfl_xor_sync(0xFFFFFFFFu, q1, m);
        }
        if (lid < 4) {
            int col = nt * 8 + lid * 2;
            psum[col * 8 + w] = s0;
            psum[(col + 1) * 8 + w] = s1;
            psq[col * 8 + w] = q0;
            psq[(col + 1) * 8 + w] = q1;
        }
    }
    __syncthreads();

    if (tid < FHID) {
        float s = 0.f, qq = 0.f;
#pragma unroll
        for (int j = 0; j < 8; j++) {
            s += psum[tid * 8 + j];
            qq += psq[tid * 8 + j];
        }
        float mean = s * (1.f / BATCH);
        float var = fmaf(-mean, mean, qq * (1.f / BATCH));   // biased variance
        float rstd = rsqrtf(var + 1e-5f);
        float a = gamma[(size_t)c * FHID + tid] * rstd;
        pa[tid] = a;
        pb[tid] = fmaf(-mean, a, beta[(size_t)c * FHID + tid]);
        pw[tid] = W2[(size_t)c * FHID + tid];
    }
    __syncthreads();

    // Transform + per-row dot: rows (w*32 + mt*16 + g_, +8)
    float rd0 = 0.f, rd1 = 0.f, rd2 = 0.f, rd3 = 0.f;
#pragma unroll
    for (int nt = 0; nt < 24; nt++) {
        int col = nt * 8 + (lid & 3) * 2;
        float a0 = pa[col], a1 = pa[col + 1];
        float b0 = pb[col], b1 = pb[col + 1];
        float w0 = pw[col], w1 = pw[col + 1];
        rd0 = fmaf(fmaxf(fmaf(a0, acc[0][nt][0], b0), 0.f), w0,
              fmaf(fmaxf(fmaf(a1, acc[0][nt][1], b1), 0.f), w1, rd0));
        rd1 = fmaf(fmaxf(fmaf(a0, acc[0][nt][2], b0), 0.f), w0,
              fmaf(fmaxf(fmaf(a1, acc[0][nt][3], b1), 0.f), w1, rd1));
        rd2 = fmaf(fmaxf(fmaf(a0, acc[1][nt][0], b0), 0.f), w0,
              fmaf(fmaxf(fmaf(a1, acc[1][nt][1], b1), 0.f), w1, rd2));
        rd3 = fmaf(fmaxf(fmaf(a0, acc[1][nt][2], b0), 0.f), w0,
              fmaf(fmaxf(fmaf(a1, acc[1][nt][3], b1), 0.f), w1, rd3));
    }
#pragma unroll
    for (int m = 1; m <= 2; m <<= 1) {
        rd0 += __shfl_xor_sync(0xFFFFFFFFu, rd0, m);
        rd1 += __shfl_xor_sync(0xFFFFFFFFu, rd1, m);
        rd2 += __shfl_xor_sync(0xFFFFFFFFu, rd2, m);
        rd3 += __shfl_xor_sync(0xFFFFFFFFu, rd3, m);
    }
    if ((lid & 3) == 0) {
        float b2c = b2[c];
        int r0 = w * 32 + g_;
        out[(size_t)(r0)      * CELLS + c] = rd0 + b2c;   // mt0, row g
        out[(size_t)(r0 + 8)  * CELLS + c] = rd1 + b2c;   // mt0, row g+8
        out[(size_t)(r0 + 16) * CELLS + c] = rd2 + b2c;   // mt1, row g
        out[(size_t)(r0 + 24) * CELLS + c] = rd3 + b2c;   // mt1, row g+8
    }
}

extern "C" void kernel_launch(void* const* d_in, const int* in_sizes, int n_in,
                              void* d_out, int out_size) {
    const float* x     = (const float*)d_in[0];
    const float* W1    = (const float*)d_in[1];
    const float* gamma = (const float*)d_in[2];
    const float* beta  = (const float*)d_in[3];
    const float* W2    = (const float*)d_in[4];
    const float* b2    = (const float*)d_in[5];
    float* out = (float*)d_out;
    (void)in_sizes; (void)n_in; (void)out_size;

    cudaFuncSetAttribute(mmlp_kernel, cudaFuncAttributeMaxDynamicSharedMemorySize,
                         SMEM_TOTAL);
    mmlp_kernel<<<CELLS, 256, SMEM_TOTAL>>>(x, W1, gamma, beta, W2, b2, out);
}

// round 9
// speedup vs baseline: 1.2616x; 1.2616x over previous
#include <cuda_runtime.h>
#include <cuda_bf16.h>
#include <cstdint>

// Problem constants (fixed shapes)
#define CELLS 4096
#define BATCH 256
#define FIN   160
#define FHID  192
#define KC    32          // K-chunk (5 chunks of 32 = 160)
#define NCHUNK 5

// bf16 operand buffer (single): padded stride 40 bf16 (80 B) -> conflict-free
// for ldmatrix 8-row phases (banks (r*20)%32 all distinct) and convert STS.
#define ASTRIDE 80        // bytes per bf16 row (32 bf16 data + 8 pad)
#define AHI 0             // A hi : 256 x 80 = 20480
#define ALO 20480         // A lo
#define BHI 40960         // B hi : 192 x 80 = 15360
#define BLO 56320         // B lo
#define BF16SZ 71680

// fp32 staging (double buffered), row stride 144 B (36 floats: 32 data + 4 pad)
// -> conflict-free LDS.128 in convert pass (banks t*4 mod 32 distinct).
#define SSTRIDE 144
#define ASTG (256 * SSTRIDE)          // 36864
#define BSTG (192 * SSTRIDE)          // 27648
#define STG0 BF16SZ                   // 71680
#define STG1 (STG0 + ASTG + BSTG)     // 136192
#define SMEM_TOTAL (STG1 + ASTG + BSTG)   // 200704

// epilogue scratch reuses stage0 region (free after last convert)
#define SM_PSUM STG0
#define SM_PSQ  (SM_PSUM + 6144)
#define SM_PA   (SM_PSQ + 6144)
#define SM_PB   (SM_PA + 768)
#define SM_PW   (SM_PB + 768)

// m16n8k16 bf16 HMMA, fp32 accumulate (sm_80+, assembles on compute_103)
#define MMA(d, a, b0, b1)                                                    \
    asm volatile(                                                            \
        "mma.sync.aligned.m16n8k16.row.col.f32.bf16.bf16.f32 "               \
        "{%0,%1,%2,%3}, {%4,%5,%6,%7}, {%8,%9}, {%0,%1,%2,%3};"              \
        : "+f"((d)[0]), "+f"((d)[1]), "+f"((d)[2]), "+f"((d)[3])             \
        : "r"((a)[0]), "r"((a)[1]), "r"((a)[2]), "r"((a)[3]),                \
          "r"(b0), "r"(b1))

#define LDM4(r, a)                                                           \
    asm volatile("ldmatrix.sync.aligned.m8n8.x4.shared.b16 {%0,%1,%2,%3}, [%4];" \
        : "=r"((r)[0]), "=r"((r)[1]), "=r"((r)[2]), "=r"((r)[3]) : "r"(a))

#define CPASYNC16(dst, src)                                                  \
    asm volatile("cp.async.cg.shared.global [%0], [%1], 16;"                 \
        :: "r"(dst), "l"(src) : "memory")
#define CPCOMMIT() asm volatile("cp.async.commit_group;" ::: "memory")
#define CPWAIT(n)  asm volatile("cp.async.wait_group %0;" :: "n"(n) : "memory")

static __device__ __forceinline__ unsigned smem_u32(const void* p) {
    unsigned a;
    asm("{ .reg .u64 t; cvta.to.shared.u64 t, %1; cvt.u32.u64 %0, t; }"
        : "=r"(a) : "l"(p));
    return a;
}

// 8 fp32 -> packed bf16 hi + bf16 lo (3xBF16 precision-recovery split)
static __device__ __forceinline__ void cvt8(const float4& A, const float4& B,
                                            uint4& hi, uint4& lo) {
    float f[8] = {A.x, A.y, A.z, A.w, B.x, B.y, B.z, B.w};
    unsigned h[4], l[4];
#pragma unroll
    for (int j = 0; j < 4; j++) {
        __nv_bfloat162 hp = __floats2bfloat162_rn(f[2 * j], f[2 * j + 1]);
        float r0 = f[2 * j]     - __bfloat162float(hp.x);
        float r1 = f[2 * j + 1] - __bfloat162float(hp.y);
        __nv_bfloat162 lp = __floats2bfloat162_rn(r0, r1);
        h[j] = *reinterpret_cast<unsigned*>(&hp);
        l[j] = *reinterpret_cast<unsigned*>(&lp);
    }
    hi = make_uint4(h[0], h[1], h[2], h[3]);
    lo = make_uint4(l[0], l[1], l[2], l[3]);
}

__global__ void __launch_bounds__(256, 1)
mmlp_kernel(const float* __restrict__ x, const float* __restrict__ W1,
            const float* __restrict__ gamma, const float* __restrict__ beta,
            const float* __restrict__ W2, const float* __restrict__ b2,
            float* __restrict__ out) {
    extern __shared__ char smem[];
    const unsigned sb = smem_u32(smem);
    const int tid = threadIdx.x;
    const int lid = tid & 31;
    const int w   = tid >> 5;          // warp id: owns batch rows [32w, 32w+32)
    const int c   = blockIdx.x;
    const int g_  = lid >> 2;          // fragment group row

    // cp.async issue for chunk k into stage at byte offset stg
    auto issue_chunk = [&](int k, unsigned stg) {
        const float* xs = x + c * (size_t)FIN + k * KC;
        const float* ws = W1 + (size_t)c * FHID * FIN + k * KC;
#pragma unroll
        for (int q = 0; q < 8; q++) {              // A: 2048 16B segs
            int s = tid + q * 256;
            int row = s >> 3, seg = s & 7;
            CPASYNC16(sb + stg + row * SSTRIDE + seg * 16,
                      xs + (size_t)row * (CELLS * FIN) + seg * 4);
        }
#pragma unroll
        for (int q = 0; q < 6; q++) {              // B: 1536 16B segs
            int s = tid + q * 256;
            int row = s >> 3, seg = s & 7;
            CPASYNC16(sb + stg + ASTG + row * SSTRIDE + seg * 16,
                      ws + (size_t)row * FIN + seg * 4);
        }
    };

    // convert stage fp32 -> bf16 hi/lo buffers (each element exactly once)
    auto convert = [&](unsigned stg) {
        // A: thread t handles row t (4 groups of 8 floats)
        {
            const char* src = smem + stg + tid * SSTRIDE;
            char* dhi = smem + AHI + tid * ASTRIDE;
            char* dlo = smem + ALO + tid * ASTRIDE;
#pragma unroll
            for (int gg = 0; gg < 4; gg++) {
                float4 v0 = *reinterpret_cast<const float4*>(src + gg * 32);
                float4 v1 = *reinterpret_cast<const float4*>(src + gg * 32 + 16);
                uint4 hi, lo;
                cvt8(v0, v1, hi, lo);
                *reinterpret_cast<uint4*>(dhi + gg * 16) = hi;
                *reinterpret_cast<uint4*>(dlo + gg * 16) = lo;
            }
        }
        // B: threads 0..191 handle row t
        if (tid < FHID) {
            const char* src = smem + stg + ASTG + tid * SSTRIDE;
            char* dhi = smem + BHI + tid * ASTRIDE;
            char* dlo = smem + BLO + tid * ASTRIDE;
#pragma unroll
            for (int gg = 0; gg < 4; gg++) {
                float4 v0 = *reinterpret_cast<const float4*>(src + gg * 32);
                float4 v1 = *reinterpret_cast<const float4*>(src + gg * 32 + 16);
                uint4 hi, lo;
                cvt8(v0, v1, hi, lo);
                *reinterpret_cast<uint4*>(dhi + gg * 16) = hi;
                *reinterpret_cast<uint4*>(dlo + gg * 16) = lo;
            }
        }
    };

    // C accumulators: warp tile 32(M) x 192(N) -> 2 m-tiles x 24 n-tiles x 4
    float acc[2][24][4];
#pragma unroll
    for (int mt = 0; mt < 2; mt++)
#pragma unroll
        for (int nt = 0; nt < 24; nt++)
#pragma unroll
            for (int j = 0; j < 4; j++) acc[mt][nt][j] = 0.f;

    // ldmatrix per-lane base addresses
    // A x4: lanes 0-7 rows+0..7, 8-15 rows+8..15, 16-23 rows k+8 (+16B), 24-31 both
    const unsigned aoff = (unsigned)((w * 32 + (lid & 15)) * ASTRIDE +
                                     (lid >> 4) * 16);
    // B x4 for nt-pair j: matrices [8j rows,k0-7],[8j,k8-15],[8j+8,k0-7],[8j+8,k8-15]
    const unsigned boff = (unsigned)((((lid >> 4) * 8) + (lid & 7)) * ASTRIDE +
                                     ((lid >> 3) & 1) * 16);

    // ---- Prologue: stage chunks 0 and 1, convert chunk 0 ----
    issue_chunk(0, STG0); CPCOMMIT();
    issue_chunk(1, STG1); CPCOMMIT();
    CPWAIT(1);
    __syncthreads();
    convert(STG0);
    __syncthreads();

    // ---- Mainloop ----
#pragma unroll 1
    for (int i = 0; i < NCHUNK; i++) {
#pragma unroll
        for (int kk = 0; kk < 2; kk++) {
            unsigned ah[2][4], al[2][4];
            unsigned ka = aoff + kk * 32;
            LDM4(ah[0], sb + AHI + ka);
            LDM4(ah[1], sb + AHI + ka + 16 * ASTRIDE);
            LDM4(al[0], sb + ALO + ka);
            LDM4(al[1], sb + ALO + ka + 16 * ASTRIDE);
#pragma unroll
            for (int j = 0; j < 12; j++) {        // nt pairs (2j, 2j+1)
                unsigned bh[4], bl[4];
                unsigned kb = boff + j * 16 * ASTRIDE + kk * 32;
                LDM4(bh, sb + BHI + kb);
                LDM4(bl, sb + BLO + kb);
#pragma unroll
                for (int mt = 0; mt < 2; mt++) {
                    MMA(acc[mt][2 * j],     ah[mt], bh[0], bh[1]);  // hi*hi
                    MMA(acc[mt][2 * j],     ah[mt], bl[0], bl[1]);  // hi*lo
                    MMA(acc[mt][2 * j],     al[mt], bh[0], bh[1]);  // lo*hi
                    MMA(acc[mt][2 * j + 1], ah[mt], bh[2], bh[3]);
                    MMA(acc[mt][2 * j + 1], ah[mt], bl[2], bl[3]);
                    MMA(acc[mt][2 * j + 1], al[mt], bh[2], bh[3]);
                }
            }
        }
        if (i < NCHUNK - 1) {
            __syncthreads();                      // all MMA reads of bf16 done
            CPWAIT(0);                            // chunk i+1 staged
            if (i + 2 < NCHUNK) {
                issue_chunk(i + 2, (i & 1) ? STG1 : STG0);
                CPCOMMIT();
            }
            convert(((i + 1) & 1) ? STG1 : STG0);
            __syncthreads();                      // bf16 buffer ready
        }
    }

    // ---- Epilogue: BN stats + folded BN + relu + W2 dot, all in regs ----
    float* psum = reinterpret_cast<float*>(smem + SM_PSUM);
    float* psq  = reinterpret_cast<float*>(smem + SM_PSQ);
    float* pa   = reinterpret_cast<float*>(smem + SM_PA);
    float* pb   = reinterpret_cast<float*>(smem + SM_PB);
    float* pw   = reinterpret_cast<float*>(smem + SM_PW);

    __syncthreads();      // everyone past MMAs before stage0 region is reused

    // Per-column partial sums over this warp's 32 rows
#pragma unroll
    for (int nt = 0; nt < 24; nt++) {
        float s0 = acc[0][nt][0] + acc[0][nt][2] + acc[1][nt][0] + acc[1][nt][2];
        float s1 = acc[0][nt][1] + acc[0][nt][3] + acc[1][nt][1] + acc[1][nt][3];
        float q0 = acc[0][nt][0] * acc[0][nt][0] + acc[0][nt][2] * acc[0][nt][2] +
                   acc[1][nt][0] * acc[1][nt][0] + acc[1][nt][2] * acc[1][nt][2];
        float q1 = acc[0][nt][1] * acc[0][nt][1] + acc[0][nt][3] * acc[0][nt][3] +
                   acc[1][nt][1] * acc[1][nt][1] + acc[1][nt][3] * acc[1][nt][3];
#pragma unroll
        for (int m = 4; m <= 16; m <<= 1) {
            s0 += __shfl_xor_sync(0xFFFFFFFFu, s0, m);
            s1 += __shfl_xor_sync(0xFFFFFFFFu, s1, m);
            q0 += __shfl_xor_sync(0xFFFFFFFFu, q0, m);
            q1 += __shfl_xor_sync(0xFFFFFFFFu, q1, m);
        }
        if (lid < 4) {
            int col = nt * 8 + lid * 2;
            psum[col * 8 + w] = s0;
            psum[(col + 1) * 8 + w] = s1;
            psq[col * 8 + w] = q0;
            psq[(col + 1) * 8 + w] = q1;
        }
    }
    __syncthreads();

    if (tid < FHID) {
        float s = 0.f, qq = 0.f;
#pragma unroll
        for (int j = 0; j < 8; j++) {
            s += psum[tid * 8 + j];
            qq += psq[tid * 8 + j];
        }
        float mean = s * (1.f / BATCH);
        float var = fmaf(-mean, mean, qq * (1.f / BATCH));   // biased variance
        float rstd = rsqrtf(var + 1e-5f);
        float a = gamma[(size_t)c * FHID + tid] * rstd;
        pa[tid] = a;
        pb[tid] = fmaf(-mean, a, beta[(size_t)c * FHID + tid]);
        pw[tid] = W2[(size_t)c * FHID + tid];
    }
    __syncthreads();

    // Transform + per-row dot: rows (w*32 + mt*16 + g_, +8)
    float rd0 = 0.f, rd1 = 0.f, rd2 = 0.f, rd3 = 0.f;
#pragma unroll
    for (int nt = 0; nt < 24; nt++) {
        int col = nt * 8 + (lid & 3) * 2;
        float a0 = pa[col], a1 = pa[col + 1];
        float b0 = pb[col], b1 = pb[col + 1];
        float w0 = pw[col], w1 = pw[col + 1];
        rd0 = fmaf(fmaxf(fmaf(a0, acc[0][nt][0], b0), 0.f), w0,
              fmaf(fmaxf(fmaf(a1, acc[0][nt][1], b1), 0.f), w1, rd0));
        rd1 = fmaf(fmaxf(fmaf(a0, acc[0][nt][2], b0), 0.f), w0,
              fmaf(fmaxf(fmaf(a1, acc[0][nt][3], b1), 0.f), w1, rd1));
        rd2 = fmaf(fmaxf(fmaf(a0, acc[1][nt][0], b0), 0.f), w0,
              fmaf(fmaxf(fmaf(a1, acc[1][nt][1], b1), 0.f), w1, rd2));
        rd3 = fmaf(fmaxf(fmaf(a0, acc[1][nt][2], b0), 0.f), w0,
              fmaf(fmaxf(fmaf(a1, acc[1][nt][3], b1), 0.f), w1, rd3));
    }
#pragma unroll
    for (int m = 1; m <= 2; m <<= 1) {
        rd0 += __shfl_xor_sync(0xFFFFFFFFu, rd0, m);
        rd1 += __shfl_xor_sync(0xFFFFFFFFu, rd1, m);
        rd2 += __shfl_xor_sync(0xFFFFFFFFu, rd2, m);
        rd3 += __shfl_xor_sync(0xFFFFFFFFu, rd3, m);
    }
    if ((lid & 3) == 0) {
        float b2c = b2[c];
        int r0 = w * 32 + g_;
        out[(size_t)(r0)      * CELLS + c] = rd0 + b2c;
        out[(size_t)(r0 + 8)  * CELLS + c] = rd1 + b2c;
        out[(size_t)(r0 + 16) * CELLS + c] = rd2 + b2c;
        out[(size_t)(r0 + 24) * CELLS + c] = rd3 + b2c;
    }
}

extern "C" void kernel_launch(void* const* d_in, const int* in_sizes, int n_in,
                              void* d_out, int out_size) {
    const float* x     = (const float*)d_in[0];
    const float* W1    = (const float*)d_in[1];
    const float* gamma = (const float*)d_in[2];
    const float* beta  = (const float*)d_in[3];
    const float* W2    = (const float*)d_in[4];
    const float* b2    = (const float*)d_in[5];
    float* out = (float*)d_out;
    (void)in_sizes; (void)n_in; (void)out_size;

    cudaFuncSetAttribute(mmlp_kernel, cudaFuncAttributeMaxDynamicSharedMemorySize,
                         SMEM_TOTAL);
    mmlp_kernel<<<CELLS, 256, SMEM_TOTAL>>>(x, W1, gamma, beta, W2, b2, out);
}